// round 1
// baseline (speedup 1.0000x reference)
#include <cuda_runtime.h>

#define BB 32     // batch
#define CH 1024   // channels C
#define SP 1024   // spatial N = H*W
#define CQ 128    // C/8

// Scratch (sanctioned __device__ globals; no runtime allocation)
__device__ float g_Q[(size_t)BB * SP * CQ];   // [b][n][o]   16 MB
__device__ float g_K[(size_t)BB * CQ * SP];   // [b][o][n]   16 MB
__device__ float g_V[(size_t)BB * CH * SP];   // [b][m][n]  128 MB

// ---------------------------------------------------------------------------
// Tiled SGEMM: Out[b][m][n] (or Out[b][n][m] if TRANS) =
//   sum_k A[m][k] * X[b][k][n] + bias[m]
// BM=BN=128, BK=16, 256 threads, 8x8 per-thread microtile.
// ---------------------------------------------------------------------------
template <bool TRANS>
__global__ void __launch_bounds__(256, 2) sgemm_proj(
    const float* __restrict__ A, const float* __restrict__ X,
    const float* __restrict__ bias, float* __restrict__ Out,
    int M, int Kd, int N)
{
    constexpr int BM = 128, BN = 128, BK = 16;
    __shared__ float As[BK][BM + 4];
    __shared__ float Xs[BK][BN + 4];

    const int b  = blockIdx.z;
    const int m0 = blockIdx.y * BM;
    const int n0 = blockIdx.x * BN;
    const int tid = threadIdx.x;
    const float* Xb = X + (size_t)b * Kd * N;

    const int mr = (tid / 16) * 8;
    const int nr = (tid % 16) * 8;

    float acc[8][8];
#pragma unroll
    for (int i = 0; i < 8; i++)
#pragma unroll
        for (int j = 0; j < 8; j++) acc[i][j] = 0.0f;

    for (int k0 = 0; k0 < Kd; k0 += BK) {
#pragma unroll
        for (int i = 0; i < 8; i++) {
            int e = tid + i * 256;          // 2048 elements per tile
            int am = e >> 4, ak = e & 15;   // A tile: 128 x 16
            As[ak][am] = A[(size_t)(m0 + am) * Kd + k0 + ak];
            int xk = e >> 7, xn = e & 127;  // X tile: 16 x 128
            Xs[xk][xn] = Xb[(size_t)(k0 + xk) * N + n0 + xn];
        }
        __syncthreads();

#pragma unroll
        for (int kk = 0; kk < BK; kk++) {
            float a[8], xr[8];
#pragma unroll
            for (int i = 0; i < 8; i++) a[i] = As[kk][mr + i];
#pragma unroll
            for (int j = 0; j < 8; j++) xr[j] = Xs[kk][nr + j];
#pragma unroll
            for (int i = 0; i < 8; i++)
#pragma unroll
                for (int j = 0; j < 8; j++)
                    acc[i][j] = fmaf(a[i], xr[j], acc[i][j]);
        }
        __syncthreads();
    }

    float bs[8];
#pragma unroll
    for (int i = 0; i < 8; i++) bs[i] = bias[m0 + mr + i];

    if (TRANS) {
#pragma unroll
        for (int j = 0; j < 8; j++)
#pragma unroll
            for (int i = 0; i < 8; i++)
                Out[((size_t)b * N + n0 + nr + j) * M + m0 + mr + i] =
                    acc[i][j] + bs[i];
    } else {
#pragma unroll
        for (int i = 0; i < 8; i++)
#pragma unroll
            for (int j = 0; j < 8; j++)
                Out[((size_t)b * M + m0 + mr + i) * N + n0 + nr + j] =
                    acc[i][j] + bs[i];
    }
}

// ---------------------------------------------------------------------------
// Fused energy -> softmax -> apply kernel.
// One block = (batch b, 32-row n-tile). 256 threads.
// Dyn smem: Qs[32][128] + Es[32][1025]  (~147.6 KB)
// ---------------------------------------------------------------------------
__global__ void __launch_bounds__(256) attn_apply(
    const float* __restrict__ x, const float* __restrict__ gamma_p,
    float* __restrict__ out)
{
    extern __shared__ float sm[];
    float* Qs = sm;               // [32][128]
    float* Es = sm + 32 * CQ;     // [32][SP+1]
    __shared__ float s_scale[32]; // gamma / rowsum per n-row
    const int ES = SP + 1;

    const int b   = blockIdx.y;
    const int n0  = blockIdx.x * 32;
    const int tid = threadIdx.x;

    // Load the 32 Q rows for this tile (contiguous in g_Q's [b][n][o] layout)
    const float* Qb = g_Q + ((size_t)b * SP + n0) * CQ;
    for (int i = tid; i < 32 * CQ; i += 256) Qs[i] = Qb[i];
    __syncthreads();

    // ---- Energy: E[nt][m] = sum_o Qs[nt][o] * K[b][o][m], 2 m's per thread ----
#pragma unroll 1
    for (int mb = 0; mb < 2; mb++) {
        const int m = mb * 512 + tid;           // covers m and m+256
        const float* Kb = g_K + (size_t)b * CQ * SP + m;
        float a0[32], a1[32];
#pragma unroll
        for (int nt = 0; nt < 32; nt++) { a0[nt] = 0.0f; a1[nt] = 0.0f; }
        for (int o = 0; o < CQ; o++) {
            float kv0 = Kb[(size_t)o * SP];
            float kv1 = Kb[(size_t)o * SP + 256];
#pragma unroll
            for (int nt = 0; nt < 32; nt++) {
                float q = Qs[nt * CQ + o];      // broadcast from smem
                a0[nt] = fmaf(q, kv0, a0[nt]);
                a1[nt] = fmaf(q, kv1, a1[nt]);
            }
        }
#pragma unroll
        for (int nt = 0; nt < 32; nt++) {
            Es[nt * ES + m]       = a0[nt];
            Es[nt * ES + m + 256] = a1[nt];
        }
    }
    __syncthreads();

    // ---- Row softmax (8 warps x 4 rows each) ----
    const float gamma = gamma_p[0];
    const int w = tid >> 5, lane = tid & 31;
    for (int nt = w * 4; nt < w * 4 + 4; nt++) {
        float mx = -1e30f;
        for (int j = lane; j < SP; j += 32) mx = fmaxf(mx, Es[nt * ES + j]);
#pragma unroll
        for (int off = 16; off; off >>= 1)
            mx = fmaxf(mx, __shfl_xor_sync(0xffffffffu, mx, off));
        float sum = 0.0f;
        for (int j = lane; j < SP; j += 32) {
            float p = __expf(Es[nt * ES + j] - mx);
            Es[nt * ES + j] = p;
            sum += p;
        }
#pragma unroll
        for (int off = 16; off; off >>= 1)
            sum += __shfl_xor_sync(0xffffffffu, sum, off);
        if (lane == 0) s_scale[nt] = gamma / sum;
    }
    __syncthreads();

    // ---- Apply: out[b][m][n0+nt] = gamma * v * att[n][m] + x ----
    // att[b][n][m] = Es[nt][m] * (1/rowsum); scale = gamma/rowsum.
    const size_t base = ((size_t)b * CH) * SP + n0;
    const int nt = tid & 31, mw = tid >> 5;
    const float scale = s_scale[nt];
#pragma unroll 4
    for (int m = mw; m < CH; m += 8) {
        size_t idx = base + (size_t)m * SP + nt;
        out[idx] = fmaf(g_V[idx] * Es[nt * ES + m], scale, x[idx]);
    }
}

// ---------------------------------------------------------------------------
extern "C" void kernel_launch(void* const* d_in, const int* in_sizes, int n_in,
                              void* d_out, int out_size)
{
    const float* x  = (const float*)d_in[0];
    const float* Wq = (const float*)d_in[1];
    const float* bq = (const float*)d_in[2];
    const float* Wk = (const float*)d_in[3];
    const float* bk = (const float*)d_in[4];
    const float* Wv = (const float*)d_in[5];
    const float* bv = (const float*)d_in[6];
    const float* gm = (const float*)d_in[7];
    float* out = (float*)d_out;

    float *pQ, *pK, *pV;
    cudaGetSymbolAddress((void**)&pQ, g_Q);
    cudaGetSymbolAddress((void**)&pK, g_K);
    cudaGetSymbolAddress((void**)&pV, g_V);

    const size_t smem = (size_t)(32 * CQ + 32 * (SP + 1)) * sizeof(float);
    cudaFuncSetAttribute(attn_apply,
                         cudaFuncAttributeMaxDynamicSharedMemorySize,
                         (int)smem);

    // Q: [b][n][o] (transposed store), K: [b][o][n], V: [b][m][n]
    sgemm_proj<true ><<<dim3(SP / 128, CQ / 128, BB), 256>>>(Wq, x, bq, pQ, CQ, CH, SP);
    sgemm_proj<false><<<dim3(SP / 128, CQ / 128, BB), 256>>>(Wk, x, bk, pK, CQ, CH, SP);
    sgemm_proj<false><<<dim3(SP / 128, CH / 128, BB), 256>>>(Wv, x, bv, pV, CH, CH, SP);
    attn_apply<<<dim3(SP / 32, BB), 256, smem>>>(x, gm, out);
}

// round 3
// speedup vs baseline: 9.7815x; 9.7815x over previous
#include <cuda_runtime.h>
#include <cuda_bf16.h>
#include <cstdint>

#define BB 32
#define CH 1024
#define SP 1024
#define CQ 128

// ---------------- scratch (device globals; no runtime alloc) ----------------
__device__ __nv_bfloat16 g_xT[(size_t)BB * SP * CH];   // [b][n][c]  64 MB
__device__ __nv_bfloat16 g_Qb[(size_t)BB * SP * CQ];   // [b][n][o]
__device__ __nv_bfloat16 g_Kb[(size_t)BB * SP * CQ];   // [b][m][o]
__device__ __nv_bfloat16 g_P [(size_t)BB * CH * SP];   // attT[b][m][n] = exp(e[n][m])
__device__ float         g_scale[(size_t)BB * SP];     // gamma / rowsum[n]
__device__ __nv_bfloat16 g_Wqb[CQ * CH];
__device__ __nv_bfloat16 g_Wkb[CQ * CH];
__device__ __nv_bfloat16 g_Wvb[(size_t)CH * CH];

// ---------------- helpers ----------------
__device__ __forceinline__ uint32_t smem_u32(const void* p) {
    uint32_t a;
    asm("{ .reg .u64 t; cvta.to.shared.u64 t, %1; cvt.u32.u64 %0, t; }" : "=r"(a) : "l"(p));
    return a;
}
#define CP16(d, s) \
    asm volatile("cp.async.cg.shared.global [%0], [%1], 16;" :: "r"(d), "l"(s) : "memory")
#define CP_COMMIT() asm volatile("cp.async.commit_group;" ::: "memory")
#define CP_WAIT0()  asm volatile("cp.async.wait_group 0;" ::: "memory")
#define CP_WAIT1()  asm volatile("cp.async.wait_group 1;" ::: "memory")

__device__ __forceinline__ void ldm_x4(uint32_t (&r)[4], uint32_t a) {
    asm volatile("ldmatrix.sync.aligned.m8n8.x4.shared.b16 {%0,%1,%2,%3}, [%4];"
        : "=r"(r[0]), "=r"(r[1]), "=r"(r[2]), "=r"(r[3]) : "r"(a));
}
__device__ __forceinline__ void mma16816(float (&c)[4], const uint32_t (&a)[4],
                                         uint32_t b0, uint32_t b1) {
    asm volatile(
        "mma.sync.aligned.m16n8k16.row.col.f32.bf16.bf16.f32 "
        "{%0,%1,%2,%3}, {%4,%5,%6,%7}, {%8,%9}, {%0,%1,%2,%3};"
        : "+f"(c[0]), "+f"(c[1]), "+f"(c[2]), "+f"(c[3])
        : "r"(a[0]), "r"(a[1]), "r"(a[2]), "r"(a[3]), "r"(b0), "r"(b1));
}
// Schraudolph fast exp (~3% max rel err) — attention path tolerates this easily.
__device__ __forceinline__ float fast_exp(float x) {
    float t = fmaf(x, 12102203.0f, 1064866805.0f);
    return __int_as_float((int)t);
}

// ---------------- kernel: fp32 -> bf16 convert ----------------
__global__ void k_cvt(const float* __restrict__ s, __nv_bfloat16* __restrict__ d, int n) {
    int i = (blockIdx.x * 256 + threadIdx.x) * 4;
    if (i < n) {
        float4 v = *reinterpret_cast<const float4*>(s + i);
        *reinterpret_cast<__nv_bfloat162*>(d + i)     = __floats2bfloat162_rn(v.x, v.y);
        *reinterpret_cast<__nv_bfloat162*>(d + i + 2) = __floats2bfloat162_rn(v.z, v.w);
    }
}

// ---------------- kernel: x[b][c][n] fp32 -> xT[b][n][c] bf16 ----------------
__global__ void __launch_bounds__(256) k_transpose(const float* __restrict__ x) {
    __shared__ float t[32][33];
    int b = blockIdx.z, c0 = blockIdx.y * 32, n0 = blockIdx.x * 32;
    int tx = threadIdx.x, ty = threadIdx.y;
    const float* src = x + ((size_t)b * CH + c0) * SP + n0;
#pragma unroll
    for (int i = 0; i < 32; i += 8) t[ty + i][tx] = src[(size_t)(ty + i) * SP + tx];
    __syncthreads();
    __nv_bfloat16* dst = g_xT + ((size_t)b * SP + n0) * CH + c0;
#pragma unroll
    for (int i = 0; i < 32; i += 8)
        dst[(size_t)(ty + i) * CH + tx] = __float2bfloat16(t[tx][ty + i]);
}

// ---------------- shared GEMM core: 128x128 tile, K=1024, BK=64 ----------------
// smem: As[2] @0 (18432 B each), Bs[2] @36864. Row stride 72 halves (144 B).
__device__ __forceinline__ void stage64(uint32_t sdst, const __nv_bfloat16* g, int tid) {
#pragma unroll
    for (int u = 0; u < 4; u++) {
        int idx = tid + u * 256, r = idx >> 3, c = idx & 7;
        CP16(sdst + r * 144 + c * 16, g + (size_t)r * CH + c * 8);
    }
}
__device__ __forceinline__ void mma_block64(uint32_t sA, uint32_t sB,
                                            float (&acc)[4][4][4], int lane, int wm, int wn) {
#pragma unroll
    for (int ks = 0; ks < 4; ks++) {
        uint32_t a[4][4];
#pragma unroll
        for (int i = 0; i < 4; i++)
            ldm_x4(a[i], sA + ((wm + i * 16 + (lane & 15)) * 72 + ks * 16 + ((lane >> 4) << 3)) * 2);
        uint32_t bf[2][4];
#pragma unroll
        for (int jp = 0; jp < 2; jp++)
            ldm_x4(bf[jp], sB + ((wn + jp * 16 + ((lane >> 4) << 3) + (lane & 7)) * 72
                                 + ks * 16 + (((lane >> 3) & 1) << 3)) * 2);
#pragma unroll
        for (int i = 0; i < 4; i++)
#pragma unroll
            for (int j = 0; j < 4; j++)
                mma16816(acc[i][j], a[i], bf[j >> 1][(j & 1) * 2], bf[j >> 1][(j & 1) * 2 + 1]);
    }
}
__device__ __forceinline__ void gemm_1024(const __nv_bfloat16* Ag, const __nv_bfloat16* Bg,
                                          uint32_t sb, float (&acc)[4][4][4],
                                          int tid, int lane, int wm, int wn) {
    const uint32_t sA0 = sb, sA1 = sb + 18432, sB0 = sb + 36864, sB1 = sb + 55296;
    stage64(sA0, Ag, tid);      stage64(sB0, Bg, tid);      CP_COMMIT();
    stage64(sA1, Ag + 64, tid); stage64(sB1, Bg + 64, tid); CP_COMMIT();
#pragma unroll 1
    for (int kc = 0; kc < 16; kc++) {
        if (kc >= 14) CP_WAIT0(); else CP_WAIT1();
        __syncthreads();
        mma_block64((kc & 1) ? sA1 : sA0, (kc & 1) ? sB1 : sB0, acc, lane, wm, wn);
        __syncthreads();
        if (kc < 14) {
            stage64((kc & 1) ? sA1 : sA0, Ag + (kc + 2) * 64, tid);
            stage64((kc & 1) ? sB1 : sB0, Bg + (kc + 2) * 64, tid);
            CP_COMMIT();
        }
    }
}
#define GEMM_SMEM 73728

// ---------------- kernel: Q/K projection ----------------
__global__ void __launch_bounds__(256, 2) k_proj(const __nv_bfloat16* __restrict__ W,
                                                 const float* __restrict__ bias,
                                                 __nv_bfloat16* __restrict__ outQ) {
    extern __shared__ char sm[];
    uint32_t sb = smem_u32(sm);
    const int tid = threadIdx.x, lane = tid & 31, wid = tid >> 5;
    const int wm = (wid >> 2) * 64, wn = (wid & 3) * 32;
    const int b = blockIdx.y, r0 = blockIdx.x * 128;

    float acc[4][4][4];
#pragma unroll
    for (int i = 0; i < 4; i++)
#pragma unroll
        for (int j = 0; j < 4; j++)
#pragma unroll
            for (int k = 0; k < 4; k++) acc[i][j][k] = 0.0f;

    gemm_1024(g_xT + ((size_t)b * SP + r0) * CH, W, sb, acc, tid, lane, wm, wn);

#pragma unroll
    for (int j = 0; j < 4; j++) {
        int col = wn + j * 8 + (lane & 3) * 2;
        float b0 = bias[col], b1 = bias[col + 1];
#pragma unroll
        for (int i = 0; i < 4; i++) {
            int rr = r0 + wm + i * 16 + (lane >> 2);
            *reinterpret_cast<__nv_bfloat162*>(&outQ[((size_t)b * SP + rr) * CQ + col]) =
                __floats2bfloat162_rn(acc[i][j][0] + b0, acc[i][j][1] + b1);
            *reinterpret_cast<__nv_bfloat162*>(&outQ[((size_t)b * SP + rr + 8) * CQ + col]) =
                __floats2bfloat162_rn(acc[i][j][2] + b0, acc[i][j][3] + b1);
        }
    }
}

// ---------------- kernel: energy + softmax (unnormalized, transposed store) ----------------
#define ELD 136
#define EA 0
#define EB 34816
#define EP 69632
#define ESUM 104448
#define EN_SMEM 104960
__global__ void __launch_bounds__(256, 2) k_energy(const float* __restrict__ gm) {
    extern __shared__ char sm[];
    uint32_t sb = smem_u32(sm);
    float* s_sum = reinterpret_cast<float*>(sm + ESUM);
    __nv_bfloat16* Ps = reinterpret_cast<__nv_bfloat16*>(sm + EP);
    const int tid = threadIdx.x, lane = tid & 31, wid = tid >> 5;
    const int wnn = (wid >> 2) * 64, wmm = (wid & 3) * 32;
    const int b = blockIdx.y, n0 = blockIdx.x * 128;

    if (tid < 128) s_sum[tid] = 0.0f;

    const __nv_bfloat16* Qg = g_Qb + ((size_t)b * SP + n0) * CQ;
    const __nv_bfloat16* Kg = g_Kb + (size_t)b * SP * CQ;
#pragma unroll
    for (int u = 0; u < 8; u++) {
        int idx = tid + u * 256, r = idx >> 4, c = idx & 15;
        CP16(sb + EA + r * 272 + c * 16, Qg + (size_t)r * CQ + c * 8);
        CP16(sb + EB + r * 272 + c * 16, Kg + (size_t)r * CQ + c * 8);
    }
    CP_COMMIT();

#pragma unroll 1
    for (int mc = 0; mc < 8; mc++) {
        CP_WAIT0();
        __syncthreads();
        float acc[4][4][4];
#pragma unroll
        for (int i = 0; i < 4; i++)
#pragma unroll
            for (int j = 0; j < 4; j++)
#pragma unroll
                for (int k = 0; k < 4; k++) acc[i][j][k] = 0.0f;
#pragma unroll
        for (int ks = 0; ks < 8; ks++) {
            uint32_t a[4][4];
#pragma unroll
            for (int i = 0; i < 4; i++)
                ldm_x4(a[i], sb + EA + ((wnn + i * 16 + (lane & 15)) * ELD
                                        + ks * 16 + ((lane >> 4) << 3)) * 2);
            uint32_t bf[2][4];
#pragma unroll
            for (int jp = 0; jp < 2; jp++)
                ldm_x4(bf[jp], sb + EB + ((wmm + jp * 16 + ((lane >> 4) << 3) + (lane & 7)) * ELD
                                          + ks * 16 + (((lane >> 3) & 1) << 3)) * 2);
#pragma unroll
            for (int i = 0; i < 4; i++)
#pragma unroll
                for (int j = 0; j < 4; j++)
                    mma16816(acc[i][j], a[i], bf[j >> 1][(j & 1) * 2], bf[j >> 1][(j & 1) * 2 + 1]);
        }
        __syncthreads();
        if (mc < 7) {
            const __nv_bfloat16* Kn = Kg + (size_t)(mc + 1) * 128 * CQ;
#pragma unroll
            for (int u = 0; u < 8; u++) {
                int idx = tid + u * 256, r = idx >> 4, c = idx & 15;
                CP16(sb + EB + r * 272 + c * 16, Kn + (size_t)r * CQ + c * 8);
            }
            CP_COMMIT();
        }
        // epilogue: exp -> Ps[m][n], rowsum
#pragma unroll
        for (int i = 0; i < 4; i++) {
            int nA = wnn + i * 16 + (lane >> 2), nB = nA + 8;
            float s0 = 0.0f, s1 = 0.0f;
#pragma unroll
            for (int j = 0; j < 4; j++) {
                int mcol = wmm + j * 8 + (lane & 3) * 2;
                float p0 = fast_exp(acc[i][j][0]), p1 = fast_exp(acc[i][j][1]);
                float p2 = fast_exp(acc[i][j][2]), p3 = fast_exp(acc[i][j][3]);
                s0 += p0 + p1; s1 += p2 + p3;
                Ps[(size_t)mcol * ELD + nA]       = __float2bfloat16(p0);
                Ps[(size_t)(mcol + 1) * ELD + nA] = __float2bfloat16(p1);
                Ps[(size_t)mcol * ELD + nB]       = __float2bfloat16(p2);
                Ps[(size_t)(mcol + 1) * ELD + nB] = __float2bfloat16(p3);
            }
            s0 += __shfl_xor_sync(0xffffffffu, s0, 1);
            s0 += __shfl_xor_sync(0xffffffffu, s0, 2);
            s1 += __shfl_xor_sync(0xffffffffu, s1, 1);
            s1 += __shfl_xor_sync(0xffffffffu, s1, 2);
            if ((lane & 3) == 0) { atomicAdd(&s_sum[nA], s0); atomicAdd(&s_sum[nB], s1); }
        }
        __syncthreads();
#pragma unroll
        for (int u = 0; u < 8; u++) {
            int idx = tid + u * 256, r = idx >> 4, c = idx & 15;
            uint4 v = *reinterpret_cast<uint4*>(sm + EP + r * 272 + c * 16);
            *reinterpret_cast<uint4*>(
                &g_P[((size_t)b * CH + mc * 128 + r) * SP + n0 + c * 8]) = v;
        }
    }
    __syncthreads();
    if (tid < 128)
        g_scale[(size_t)b * SP + n0 + tid] = gm[0] / s_sum[tid];
}

// ---------------- kernel: V GEMM fused with apply ----------------
__global__ void __launch_bounds__(256, 2) k_vapply(const float* __restrict__ bv,
                                                   const float* __restrict__ x,
                                                   float* __restrict__ out) {
    extern __shared__ char sm[];
    uint32_t sb = smem_u32(sm);
    const int tid = threadIdx.x, lane = tid & 31, wid = tid >> 5;
    const int wm = (wid >> 2) * 64, wn = (wid & 3) * 32;
    const int b = blockIdx.z, m0 = blockIdx.y * 128, n0 = blockIdx.x * 128;

    float acc[4][4][4];
#pragma unroll
    for (int i = 0; i < 4; i++)
#pragma unroll
        for (int j = 0; j < 4; j++)
#pragma unroll
            for (int k = 0; k < 4; k++) acc[i][j][k] = 0.0f;

    gemm_1024(g_Wvb + (size_t)m0 * CH, g_xT + ((size_t)b * SP + n0) * CH,
              sb, acc, tid, lane, wm, wn);

#pragma unroll
    for (int i = 0; i < 4; i++) {
        int mA = m0 + wm + i * 16 + (lane >> 2), mB = mA + 8;
        float bvA = bv[mA], bvB = bv[mB];
#pragma unroll
        for (int j = 0; j < 4; j++) {
            int n = n0 + wn + j * 8 + (lane & 3) * 2;
            size_t pa = ((size_t)b * CH + mA) * SP + n;
            size_t pb = ((size_t)b * CH + mB) * SP + n;
            float2 sc = *reinterpret_cast<const float2*>(&g_scale[(size_t)b * SP + n]);
            __nv_bfloat162 PA = *reinterpret_cast<const __nv_bfloat162*>(&g_P[pa]);
            __nv_bfloat162 PB = *reinterpret_cast<const __nv_bfloat162*>(&g_P[pb]);
            float2 xa = *reinterpret_cast<const float2*>(&x[pa]);
            float2 xb = *reinterpret_cast<const float2*>(&x[pb]);
            float2 oa, ob;
            oa.x = fmaf((acc[i][j][0] + bvA) * __bfloat162float(PA.x), sc.x, xa.x);
            oa.y = fmaf((acc[i][j][1] + bvA) * __bfloat162float(PA.y), sc.y, xa.y);
            ob.x = fmaf((acc[i][j][2] + bvB) * __bfloat162float(PB.x), sc.x, xb.x);
            ob.y = fmaf((acc[i][j][3] + bvB) * __bfloat162float(PB.y), sc.y, xb.y);
            *reinterpret_cast<float2*>(&out[pa]) = oa;
            *reinterpret_cast<float2*>(&out[pb]) = ob;
        }
    }
}

// ---------------- launcher ----------------
extern "C" void kernel_launch(void* const* d_in, const int* in_sizes, int n_in,
                              void* d_out, int out_size) {
    const float* x  = (const float*)d_in[0];
    const float* Wq = (const float*)d_in[1];
    const float* bq = (const float*)d_in[2];
    const float* Wk = (const float*)d_in[3];
    const float* bk = (const float*)d_in[4];
    const float* Wv = (const float*)d_in[5];
    const float* bv = (const float*)d_in[6];
    const float* gm = (const float*)d_in[7];
    float* out = (float*)d_out;

    __nv_bfloat16 *pWq, *pWk, *pWv, *pQ, *pK;
    cudaGetSymbolAddress((void**)&pWq, g_Wqb);
    cudaGetSymbolAddress((void**)&pWk, g_Wkb);
    cudaGetSymbolAddress((void**)&pWv, g_Wvb);
    cudaGetSymbolAddress((void**)&pQ,  g_Qb);
    cudaGetSymbolAddress((void**)&pK,  g_Kb);

    cudaFuncSetAttribute(k_proj,   cudaFuncAttributeMaxDynamicSharedMemorySize, GEMM_SMEM);
    cudaFuncSetAttribute(k_vapply, cudaFuncAttributeMaxDynamicSharedMemorySize, GEMM_SMEM);
    cudaFuncSetAttribute(k_energy, cudaFuncAttributeMaxDynamicSharedMemorySize, EN_SMEM);

    k_cvt<<<CQ * CH / 1024, 256>>>(Wq, pWq, CQ * CH);
    k_cvt<<<CQ * CH / 1024, 256>>>(Wk, pWk, CQ * CH);
    k_cvt<<<CH * CH / 1024, 256>>>(Wv, pWv, CH * CH);
    k_transpose<<<dim3(SP / 32, CH / 32, BB), dim3(32, 8)>>>(x);
    k_proj<<<dim3(8, BB), 256, GEMM_SMEM>>>(pWq, bq, pQ);
    k_proj<<<dim3(8, BB), 256, GEMM_SMEM>>>(pWk, bk, pK);
    k_energy<<<dim3(8, BB), 256, EN_SMEM>>>(gm);
    k_vapply<<<dim3(8, 8, BB), 256, GEMM_SMEM>>>(bv, x, out);
}